// round 1
// baseline (speedup 1.0000x reference)
#include <cuda_runtime.h>
#include <cstdint>

#define L_ 128
#define B_ 4096
#define D_ 300
#define T_ (L_*B_)          // 524288 tokens
#define KP 304              // padded K (38 * 8)
#define NP 320              // padded N (8 warps * 40)
#define NKSTEP (KP/8)       // 38
#define SROW 308            // S smem row stride (308 % 32 == 20 -> conflict-free A frag loads)
#define WROW 328            // W slice smem row stride (328 % 32 == 8 -> conflict-free B frag loads)
#define MT 128              // tokens per block
#define SMEM_FLOATS (MT*SROW + 2*8*WROW + 8*MT)   // 45696 floats = 182784 B

__device__ float g_Ws[KP*NP];   // symmetrized, tf32-rounded, zero-padded
__device__ float g_q[T_];       // s^T Ws s
__device__ float g_c[T_];       // s_{l+1}^T Ws s_l  (0 for l = L-1)

__device__ __forceinline__ float rnd_tf32(float x){
    float r; asm("cvt.rna.tf32.f32 %0, %1;" : "=f"(r) : "f"(x)); return r;
}

__device__ __forceinline__ void cp16(void* smem_dst, const void* gsrc){
    unsigned sa = (unsigned)__cvta_generic_to_shared(smem_dst);
    asm volatile("cp.async.cg.shared.global [%0], [%1], 16;" :: "r"(sa), "l"(gsrc));
}

__device__ __forceinline__ void load_wslice(float* sWbuf, const float* gsrc, int tid){
    // 8 rows x 320 floats = 640 x 16B chunks
    for (int i = tid; i < 640; i += 512){
        int r = i / 80, c = (i % 80) * 4;
        cp16(sWbuf + r*WROW + c, gsrc + r*NP + c);
    }
}

// ---------------- pass 0: Ws = tf32_round((W + W^T)/2), zero-padded ----------------
__global__ void pass0_symW(const float* __restrict__ W){
    int idx = blockIdx.x * blockDim.x + threadIdx.x;
    if (idx >= KP*NP) return;
    int d = idx / NP, e = idx % NP;
    float v = 0.f;
    if (d < D_ && e < D_) v = 0.5f * (W[d*D_ + e] + W[e*D_ + d]);
    g_Ws[idx] = rnd_tf32(v);
}

// ---------------- pass 1: fused GEMM (Z = S*Ws) + row dots -> q, c ----------------
__global__ __launch_bounds__(512, 1)
void pass1_scores(const float* __restrict__ sent){
    extern __shared__ float sm[];
    float* sS    = sm;                      // [MT][SROW]
    float* sW    = sm + MT*SROW;            // [2][8][WROW]
    float* sPart = sW + 2*8*WROW;           // [8][MT]

    const int tid  = threadIdx.x;
    const int warp = tid >> 5, lane = tid & 31;
    const int g = lane >> 2, t4 = lane & 3;
    const int wm = warp >> 3, wn = warp & 7;      // 2 x 8 warp grid
    const long t0 = (long)blockIdx.x * MT;
    const int  l  = (int)(t0 / B_);               // uniform in block (128 | 4096)

    // stage S tile (tf32-rounded), k-pad with zeros
    {
        const float4* src = reinterpret_cast<const float4*>(sent + t0 * D_);
        for (int i = tid; i < MT*D_/4; i += 512){
            float4 v = src[i];
            int row = i / (D_/4);
            int col = (i % (D_/4)) * 4;
            float* p = sS + row*SROW + col;
            p[0]=rnd_tf32(v.x); p[1]=rnd_tf32(v.y); p[2]=rnd_tf32(v.z); p[3]=rnd_tf32(v.w);
        }
        for (int i = tid; i < MT*8; i += 512)
            sS[(i>>3)*SROW + D_ + (i&7)] = 0.f;
    }
    load_wslice(sW, g_Ws, tid);
    asm volatile("cp.async.commit_group;" ::: "memory");
    asm volatile("cp.async.wait_group 0;" ::: "memory");
    __syncthreads();

    float acc[4][5][4];
    #pragma unroll
    for (int i=0;i<4;i++)
        #pragma unroll
        for (int j=0;j<5;j++)
            #pragma unroll
            for (int k=0;k<4;k++) acc[i][j][k] = 0.f;

    const int arow0 = wm * 64;   // warp token base within tile
    const int ncol0 = wn * 40;   // warp e base

    for (int kk = 0; kk < NKSTEP; kk++){
        float* wbuf = sW + (kk & 1) * (8*WROW);
        if (kk + 1 < NKSTEP){
            load_wslice(sW + ((kk+1)&1)*(8*WROW), g_Ws + (kk+1)*8*NP, tid);
            asm volatile("cp.async.commit_group;" ::: "memory");
        }
        const int k0 = kk * 8;
        unsigned a[4][4], b[5][2];
        #pragma unroll
        for (int mf = 0; mf < 4; mf++){
            const float* base = sS + (arow0 + mf*16 + g)*SROW + k0 + t4;
            a[mf][0] = __float_as_uint(base[0]);
            a[mf][1] = __float_as_uint(base[8*SROW]);
            a[mf][2] = __float_as_uint(base[4]);
            a[mf][3] = __float_as_uint(base[8*SROW + 4]);
        }
        #pragma unroll
        for (int nf = 0; nf < 5; nf++){
            const float* bb = wbuf + t4*WROW + ncol0 + nf*8 + g;
            b[nf][0] = __float_as_uint(bb[0]);
            b[nf][1] = __float_as_uint(bb[4*WROW]);
        }
        #pragma unroll
        for (int mf = 0; mf < 4; mf++)
            #pragma unroll
            for (int nf = 0; nf < 5; nf++)
                asm volatile(
                    "mma.sync.aligned.m16n8k8.row.col.f32.tf32.tf32.f32 "
                    "{%0,%1,%2,%3},{%4,%5,%6,%7},{%8,%9},{%0,%1,%2,%3};"
                    : "+f"(acc[mf][nf][0]), "+f"(acc[mf][nf][1]),
                      "+f"(acc[mf][nf][2]), "+f"(acc[mf][nf][3])
                    : "r"(a[mf][0]), "r"(a[mf][1]), "r"(a[mf][2]), "r"(a[mf][3]),
                      "r"(b[nf][0]), "r"(b[nf][1]));
        asm volatile("cp.async.wait_group 0;" ::: "memory");
        __syncthreads();
    }

    // ---- q epilogue: q[row] = sum_e z[row][e] * s[row][e] ----
    #pragma unroll
    for (int mf = 0; mf < 4; mf++){
        #pragma unroll
        for (int h = 0; h < 2; h++){
            const int rloc = arow0 + mf*16 + h*8 + g;
            float part = 0.f;
            #pragma unroll
            for (int nf = 0; nf < 5; nf++)
                #pragma unroll
                for (int j = 0; j < 2; j++){
                    int e = ncol0 + nf*8 + 2*t4 + j;
                    if (e < D_) part += acc[mf][nf][h*2 + j] * sS[rloc*SROW + e];
                }
            part += __shfl_xor_sync(0xffffffffu, part, 1);
            part += __shfl_xor_sync(0xffffffffu, part, 2);
            if (t4 == 0) sPart[wn*MT + rloc] = part;
        }
    }
    __syncthreads();
    if (tid < MT){
        float v = 0.f;
        #pragma unroll
        for (int w = 0; w < 8; w++) v += sPart[w*MT + tid];
        g_q[t0 + tid] = v;
    }
    // restage sS with next-l rows (raw, no rounding) for the cross dot
    if (l < L_-1){
        const float4* src = reinterpret_cast<const float4*>(sent + (t0 + B_) * D_);
        for (int i = tid; i < MT*D_/4; i += 512){
            float4 v = src[i];
            int row = i / (D_/4);
            int col = (i % (D_/4)) * 4;
            float* p = sS + row*SROW + col;
            p[0]=v.x; p[1]=v.y; p[2]=v.z; p[3]=v.w;
        }
    }
    __syncthreads();
    if (l < L_-1){
        #pragma unroll
        for (int mf = 0; mf < 4; mf++){
            #pragma unroll
            for (int h = 0; h < 2; h++){
                const int rloc = arow0 + mf*16 + h*8 + g;
                float part = 0.f;
                #pragma unroll
                for (int nf = 0; nf < 5; nf++)
                    #pragma unroll
                    for (int j = 0; j < 2; j++){
                        int e = ncol0 + nf*8 + 2*t4 + j;
                        if (e < D_) part += acc[mf][nf][h*2 + j] * sS[rloc*SROW + e];
                    }
                part += __shfl_xor_sync(0xffffffffu, part, 1);
                part += __shfl_xor_sync(0xffffffffu, part, 2);
                if (t4 == 0) sPart[wn*MT + rloc] = part;
            }
        }
    }
    __syncthreads();
    if (tid < MT){
        float v = 0.f;
        if (l < L_-1){
            #pragma unroll
            for (int w = 0; w < 8; w++) v += sPart[w*MT + tid];
        }
        g_c[t0 + tid] = v;
    }
}

// ---------------- pass 2: masked 3-way softmax + neighbor combine ----------------
__global__ void pass2_combine(const float* __restrict__ sent, const int* __restrict__ size,
                              float* __restrict__ out){
    const int lane = threadIdx.x & 31;
    int wid = (blockIdx.x * blockDim.x + threadIdx.x) >> 5;
    const int nw = (gridDim.x * blockDim.x) >> 5;
    const float NEG = __int_as_float(0xff800000);   // -inf
    const float INVD = 1.0f / (float)D_;
    for (int t = wid; t < T_; t += nw){
        int l = t >> 12;             // t / 4096
        int b = t & (B_ - 1);
        int sz = size[b];
        float l1 = g_q[t] * INVD;
        float l0 = (l >= 1   && l < sz    ) ? g_c[t - B_] * INVD : NEG;
        float l2 = (l < L_-1 && l < sz - 1) ? g_c[t]      * INVD : NEG;
        float m  = fmaxf(l1, fmaxf(l0, l2));
        float e0 = expf(l0 - m), e1 = expf(l1 - m), e2 = expf(l2 - m);
        float inv = 1.0f / (e0 + e1 + e2);
        float w0 = e0 * inv, w1 = e1 * inv, w2 = e2 * inv;
        const float* r1 = sent + (size_t)t * D_;
        float*       o  = out  + (size_t)t * D_;
        const float* r0 = r1 - (size_t)B_ * D_;
        const float* r2 = r1 + (size_t)B_ * D_;
        bool hp = (l > 0), hn = (l < L_-1);
        for (int d = lane; d < D_; d += 32){
            float v = w1 * r1[d];
            if (hp) v += w0 * r0[d];
            if (hn) v += w2 * r2[d];
            o[d] = v;
        }
    }
}

extern "C" void kernel_launch(void* const* d_in, const int* in_sizes, int n_in,
                              void* d_out, int out_size){
    const float* sent = nullptr;
    const int*   size = nullptr;
    const float* W    = nullptr;
    for (int i = 0; i < n_in; i++){
        if      (in_sizes[i] == L_*B_*D_) sent = (const float*)d_in[i];
        else if (in_sizes[i] == B_)       size = (const int*)d_in[i];
        else if (in_sizes[i] == D_*D_)    W    = (const float*)d_in[i];
    }
    float* out = (float*)d_out;

    cudaFuncSetAttribute(pass1_scores, cudaFuncAttributeMaxDynamicSharedMemorySize,
                         SMEM_FLOATS * (int)sizeof(float));

    pass0_symW<<<(KP*NP + 255)/256, 256>>>(W);
    pass1_scores<<<T_/MT, 512, SMEM_FLOATS * (int)sizeof(float)>>>(sent);
    pass2_combine<<<8192, 256>>>(sent, size, out);
}

// round 3
// speedup vs baseline: 1.7392x; 1.7392x over previous
#include <cuda_runtime.h>
#include <cuda_bf16.h>
#include <cstdint>

#define L_ 128
#define B_ 4096
#define D_ 300
#define T_ (L_*B_)          // 524288 tokens
#define KP 320              // padded K (4 chunks * 80)
#define NP 320              // padded N (8 warps * 40)
#define KCH 80              // K rows per chunk
#define NCHUNK 4
#define SROWB 328           // S smem row stride (bf16)
#define WROWB 328           // W smem row stride (bf16)
#define MT 128              // tokens per block

// smem bytes: S 128*328*2 = 83968 ; W 2*80*328*2 = 104960 ; partials 8*128*4 = 4096
#define SMEM_BYTES (128*SROWB*2 + 2*KCH*WROWB*2 + 8*MT*4)   // 193024

__device__ __nv_bfloat16 g_Wsb[KP*NP];  // symmetrized bf16, zero-padded
__device__ float g_q[T_];               // s^T Ws s
__device__ float g_c[T_];               // s_{l+1}^T Ws s_l (0 for l = L-1)

__device__ __forceinline__ void cp16(void* smem_dst, const void* gsrc){
    unsigned sa = (unsigned)__cvta_generic_to_shared(smem_dst);
    asm volatile("cp.async.cg.shared.global [%0], [%1], 16;" :: "r"(sa), "l"(gsrc));
}
__device__ __forceinline__ void ldmA4(unsigned& r0, unsigned& r1, unsigned& r2, unsigned& r3, const void* p){
    unsigned a = (unsigned)__cvta_generic_to_shared(p);
    asm volatile("ldmatrix.sync.aligned.m8n8.x4.shared.b16 {%0,%1,%2,%3},[%4];"
                 : "=r"(r0),"=r"(r1),"=r"(r2),"=r"(r3) : "r"(a));
}
__device__ __forceinline__ void ldmBT4(unsigned& r0, unsigned& r1, unsigned& r2, unsigned& r3, const void* p){
    unsigned a = (unsigned)__cvta_generic_to_shared(p);
    asm volatile("ldmatrix.sync.aligned.m8n8.x4.trans.shared.b16 {%0,%1,%2,%3},[%4];"
                 : "=r"(r0),"=r"(r1),"=r"(r2),"=r"(r3) : "r"(a));
}
__device__ __forceinline__ void ldmBT2(unsigned& r0, unsigned& r1, const void* p){
    unsigned a = (unsigned)__cvta_generic_to_shared(p);
    asm volatile("ldmatrix.sync.aligned.m8n8.x2.trans.shared.b16 {%0,%1},[%2];"
                 : "=r"(r0),"=r"(r1) : "r"(a));
}

// ---------------- pass 0: Wsb = bf16((W + W^T)/2), zero-padded [KP][NP] ----------------
__global__ void pass0_symW(const float* __restrict__ W){
    int idx = blockIdx.x * blockDim.x + threadIdx.x;
    if (idx >= KP*NP) return;
    int d = idx / NP, e = idx % NP;
    float v = 0.f;
    if (d < D_ && e < D_) v = 0.5f * (W[d*D_ + e] + W[e*D_ + d]);
    g_Wsb[idx] = __float2bfloat16(v);
}

// ---------------- pass 1: fused GEMM (Z = S*Ws) + row dots -> q, c ----------------
__global__ __launch_bounds__(512, 1)
void pass1_scores(const float* __restrict__ sent){
    extern __shared__ __align__(16) unsigned char smraw[];
    __nv_bfloat16* sS = (__nv_bfloat16*)smraw;              // [128][SROWB]
    __nv_bfloat16* sW = sS + 128*SROWB;                     // [2][KCH][WROWB]
    float* sPart = (float*)(sW + 2*KCH*WROWB);              // [8][MT]

    const int tid  = threadIdx.x;
    const int warp = tid >> 5, lane = tid & 31;
    const int g = lane >> 2, t4 = lane & 3;
    const int wm = warp >> 3, wn = warp & 7;                // 2 x 8 warp grid
    const long t0 = (long)blockIdx.x * MT;
    const int  l  = (int)(t0 / B_);                         // uniform in block

    const int arow0 = wm * 64;
    const int ncol0 = wn * 40;
    // ldmatrix lane geometry
    const int rF = (lane & 7) + ((lane >> 3) & 1) * 8;      // row within 16
    const int cF = (lane >> 4) * 8;                         // col-half select

    // issue W chunk 0 load first
    {
        const __nv_bfloat16* src = g_Wsb;
        for (int i = tid; i < KCH*40; i += 512){
            int r = i / 40, c = (i % 40) * 8;
            cp16(sW + r*WROWB + c, src + r*NP + c);
        }
        asm volatile("cp.async.commit_group;" ::: "memory");
    }

    // stage S tile (fp32 -> bf16), pad cols [300,320) with zero
    {
        const float4* src = reinterpret_cast<const float4*>(sent + t0 * D_);
        for (int i = tid; i < MT*D_/4; i += 512){
            float4 v = src[i];
            int row = i / (D_/4);
            int col = (i % (D_/4)) * 4;
            __nv_bfloat16* p = sS + row*SROWB + col;
            p[0]=__float2bfloat16(v.x); p[1]=__float2bfloat16(v.y);
            p[2]=__float2bfloat16(v.z); p[3]=__float2bfloat16(v.w);
        }
        for (int i = tid; i < MT*(KP-D_); i += 512){
            int row = i / (KP-D_), col = D_ + i % (KP-D_);
            sS[row*SROWB + col] = __float2bfloat16(0.f);
        }
    }

    float acc[4][5][4];
    #pragma unroll
    for (int i=0;i<4;i++)
        #pragma unroll
        for (int j=0;j<5;j++)
            #pragma unroll
            for (int k=0;k<4;k++) acc[i][j][k] = 0.f;

    for (int ch = 0; ch < NCHUNK; ch++){
        if (ch + 1 < NCHUNK){
            const __nv_bfloat16* src = g_Wsb + (ch+1)*KCH*NP;
            __nv_bfloat16* dst = sW + ((ch+1)&1)*(KCH*WROWB);
            for (int i = tid; i < KCH*40; i += 512){
                int r = i / 40, c = (i % 40) * 8;
                cp16(dst + r*WROWB + c, src + r*NP + c);
            }
            asm volatile("cp.async.commit_group;" ::: "memory");
            asm volatile("cp.async.wait_group 1;" ::: "memory");
        } else {
            asm volatile("cp.async.wait_group 0;" ::: "memory");
        }
        __syncthreads();

        const __nv_bfloat16* wbuf = sW + (ch&1)*(KCH*WROWB);
        const int kbase = ch * KCH;
        #pragma unroll
        for (int ks = 0; ks < KCH/16; ks++){
            const int k0s = kbase + ks*16;   // col in sS
            const int k0w = ks*16;           // row in wbuf
            unsigned b[5][2];
            ldmBT4(b[0][0],b[0][1],b[1][0],b[1][1], wbuf + (k0w + rF)*WROWB + ncol0 + cF);
            ldmBT4(b[2][0],b[2][1],b[3][0],b[3][1], wbuf + (k0w + rF)*WROWB + ncol0 + 16 + cF);
            ldmBT2(b[4][0],b[4][1],                 wbuf + (k0w + rF)*WROWB + ncol0 + 32);
            #pragma unroll
            for (int mf = 0; mf < 4; mf++){
                unsigned a0,a1,a2,a3;
                ldmA4(a0,a1,a2,a3, sS + (arow0 + mf*16 + rF)*SROWB + k0s + cF);
                #pragma unroll
                for (int nf = 0; nf < 5; nf++)
                    asm volatile(
                        "mma.sync.aligned.m16n8k16.row.col.f32.bf16.bf16.f32 "
                        "{%0,%1,%2,%3},{%4,%5,%6,%7},{%8,%9},{%0,%1,%2,%3};"
                        : "+f"(acc[mf][nf][0]), "+f"(acc[mf][nf][1]),
                          "+f"(acc[mf][nf][2]), "+f"(acc[mf][nf][3])
                        : "r"(a0), "r"(a1), "r"(a2), "r"(a3),
                          "r"(b[nf][0]), "r"(b[nf][1]));
            }
        }
        __syncthreads();
    }

    // ---- q epilogue: q[row] = sum_e z[row][e] * s[row][e] ----
    #pragma unroll
    for (int mf = 0; mf < 4; mf++){
        #pragma unroll
        for (int h = 0; h < 2; h++){
            const int rloc = arow0 + mf*16 + h*8 + g;
            float part = 0.f;
            #pragma unroll
            for (int nf = 0; nf < 5; nf++)
                #pragma unroll
                for (int j = 0; j < 2; j++){
                    int e = ncol0 + nf*8 + 2*t4 + j;
                    if (e < D_) part += acc[mf][nf][h*2 + j] * __bfloat162float(sS[rloc*SROWB + e]);
                }
            part += __shfl_xor_sync(0xffffffffu, part, 1);
            part += __shfl_xor_sync(0xffffffffu, part, 2);
            if (t4 == 0) sPart[wn*MT + rloc] = part;
        }
    }
    __syncthreads();
    if (tid < MT){
        float v = 0.f;
        #pragma unroll
        for (int w = 0; w < 8; w++) v += sPart[w*MT + tid];
        g_q[t0 + tid] = v;
    }
    // restage sS with next-l rows (bf16) for the cross dot
    if (l < L_-1){
        const float4* src = reinterpret_cast<const float4*>(sent + (t0 + B_) * D_);
        for (int i = tid; i < MT*D_/4; i += 512){
            float4 v = src[i];
            int row = i / (D_/4);
            int col = (i % (D_/4)) * 4;
            __nv_bfloat16* p = sS + row*SROWB + col;
            p[0]=__float2bfloat16(v.x); p[1]=__float2bfloat16(v.y);
            p[2]=__float2bfloat16(v.z); p[3]=__float2bfloat16(v.w);
        }
    }
    __syncthreads();
    if (l < L_-1){
        #pragma unroll
        for (int mf = 0; mf < 4; mf++){
            #pragma unroll
            for (int h = 0; h < 2; h++){
                const int rloc = arow0 + mf*16 + h*8 + g;
                float part = 0.f;
                #pragma unroll
                for (int nf = 0; nf < 5; nf++)
                    #pragma unroll
                    for (int j = 0; j < 2; j++){
                        int e = ncol0 + nf*8 + 2*t4 + j;
                        if (e < D_) part += acc[mf][nf][h*2 + j] * __bfloat162float(sS[rloc*SROWB + e]);
                    }
                part += __shfl_xor_sync(0xffffffffu, part, 1);
                part += __shfl_xor_sync(0xffffffffu, part, 2);
                if (t4 == 0) sPart[wn*MT + rloc] = part;
            }
        }
    }
    __syncthreads();
    if (tid < MT){
        float v = 0.f;
        if (l < L_-1){
            #pragma unroll
            for (int w = 0; w < 8; w++) v += sPart[w*MT + tid];
        }
        g_c[t0 + tid] = v;
    }
}

// ---------------- pass 2: masked 3-way softmax + neighbor combine ----------------
__global__ void pass2_combine(const float* __restrict__ sent, const int* __restrict__ size,
                              float* __restrict__ out){
    const int lane = threadIdx.x & 31;
    int wid = (blockIdx.x * blockDim.x + threadIdx.x) >> 5;
    const int nw = (gridDim.x * blockDim.x) >> 5;
    const float NEG = __int_as_float(0xff800000);   // -inf
    const float INVD = 1.0f / (float)D_;
    for (int t = wid; t < T_; t += nw){
        int l = t >> 12;
        int b = t & (B_ - 1);
        int sz = size[b];
        float l1 = g_q[t] * INVD;
        float l0 = (l >= 1   && l < sz    ) ? g_c[t - B_] * INVD : NEG;
        float l2 = (l < L_-1 && l < sz - 1) ? g_c[t]      * INVD : NEG;
        float m  = fmaxf(l1, fmaxf(l0, l2));
        float e0 = expf(l0 - m), e1 = expf(l1 - m), e2 = expf(l2 - m);
        float inv = 1.0f / (e0 + e1 + e2);
        float w0 = e0 * inv, w1 = e1 * inv, w2 = e2 * inv;
        const float4* r1 = reinterpret_cast<const float4*>(sent + (size_t)t * D_);
        float4*       o  = reinterpret_cast<float4*>(out + (size_t)t * D_);
        const float4* r0 = r1 - (size_t)B_ * (D_/4);
        const float4* r2 = r1 + (size_t)B_ * (D_/4);
        bool hp = (l > 0), hn = (l < L_-1);
        for (int d = lane; d < D_/4; d += 32){
            float4 v1 = r1[d];
            float4 v; v.x = w1*v1.x; v.y = w1*v1.y; v.z = w1*v1.z; v.w = w1*v1.w;
            if (hp){ float4 v0 = r0[d]; v.x += w0*v0.x; v.y += w0*v0.y; v.z += w0*v0.z; v.w += w0*v0.w; }
            if (hn){ float4 v2 = r2[d]; v.x += w2*v2.x; v.y += w2*v2.y; v.z += w2*v2.z; v.w += w2*v2.w; }
            o[d] = v;
        }
    }
}

extern "C" void kernel_launch(void* const* d_in, const int* in_sizes, int n_in,
                              void* d_out, int out_size){
    const float* sent = nullptr;
    const int*   size = nullptr;
    const float* W    = nullptr;
    for (int i = 0; i < n_in; i++){
        if      (in_sizes[i] == L_*B_*D_) sent = (const float*)d_in[i];
        else if (in_sizes[i] == B_)       size = (const int*)d_in[i];
        else if (in_sizes[i] == D_*D_)    W    = (const float*)d_in[i];
    }
    float* out = (float*)d_out;

    cudaFuncSetAttribute(pass1_scores, cudaFuncAttributeMaxDynamicSharedMemorySize, SMEM_BYTES);

    pass0_symW<<<(KP*NP + 255)/256, 256>>>(W);
    pass1_scores<<<T_/MT, 512, SMEM_BYTES>>>(sent);
    pass2_combine<<<8192, 256>>>(sent, size, out);
}

// round 5
// speedup vs baseline: 2.0861x; 1.1994x over previous
#include <cuda_runtime.h>
#include <cuda_bf16.h>
#include <cstdint>

#define L_ 128
#define B_ 4096
#define D_ 300
#define T_ (L_*B_)          // 524288 tokens
#define KP 320              // padded K (10 chunks * 32)
#define NP 320              // padded N (8 warps * 40)
#define KCH 32              // K rows per chunk
#define NCHUNKS 10
#define MT 64               // tokens per block (M)
#define SROWB 328           // S smem row stride (bf16)
#define WROWB 328           // W smem row stride (bf16)

// smem layout (bytes)
#define SMEM_S  0                          // 64*328*2   = 41984
#define SMEM_W  41984                      // 3*32*328*2 = 62976
#define SMEM_PQ 104960                     // 8*64*4     = 2048
#define SMEM_PC 107008                     // 2048
#define SMEM_TOTAL 109056

__device__ __nv_bfloat16 g_Wsb[KP*NP];  // symmetrized bf16 [k][n], zero-padded
__device__ float g_q[T_];               // s^T Ws s
__device__ float g_c[T_];               // s_{l+1}^T Ws s_l (0 for l = L-1)

__device__ __forceinline__ void cp16(void* smem_dst, const void* gsrc){
    unsigned sa = (unsigned)__cvta_generic_to_shared(smem_dst);
    asm volatile("cp.async.cg.shared.global [%0], [%1], 16;" :: "r"(sa), "l"(gsrc));
}
__device__ __forceinline__ void ldmA4(unsigned& r0, unsigned& r1, unsigned& r2, unsigned& r3, const void* p){
    unsigned a = (unsigned)__cvta_generic_to_shared(p);
    asm volatile("ldmatrix.sync.aligned.m8n8.x4.shared.b16 {%0,%1,%2,%3},[%4];"
                 : "=r"(r0),"=r"(r1),"=r"(r2),"=r"(r3) : "r"(a));
}
__device__ __forceinline__ void ldmBT4(unsigned& r0, unsigned& r1, unsigned& r2, unsigned& r3, const void* p){
    unsigned a = (unsigned)__cvta_generic_to_shared(p);
    asm volatile("ldmatrix.sync.aligned.m8n8.x4.trans.shared.b16 {%0,%1,%2,%3},[%4];"
                 : "=r"(r0),"=r"(r1),"=r"(r2),"=r"(r3) : "r"(a));
}
__device__ __forceinline__ void ldmBT2(unsigned& r0, unsigned& r1, const void* p){
    unsigned a = (unsigned)__cvta_generic_to_shared(p);
    asm volatile("ldmatrix.sync.aligned.m8n8.x2.trans.shared.b16 {%0,%1},[%2];"
                 : "=r"(r0),"=r"(r1) : "r"(a));
}

// ---------------- pass 0: Wsb = bf16((W + W^T)/2), zero-padded [KP][NP] ----------------
__global__ void pass0_symW(const float* __restrict__ W){
    int idx = blockIdx.x * blockDim.x + threadIdx.x;
    if (idx >= KP*NP) return;
    int d = idx / NP, e = idx % NP;
    float v = 0.f;
    if (d < D_ && e < D_) v = 0.5f * (W[d*D_ + e] + W[e*D_ + d]);
    g_Wsb[idx] = __float2bfloat16(v);
}

// ---------------- pass 1: fused GEMM (Z = S*Ws) + row dots -> q, c ----------------
__global__ __launch_bounds__(256, 2)
void pass1_scores(const float* __restrict__ sent){
    extern __shared__ __align__(16) unsigned char smraw[];
    __nv_bfloat16* sS = (__nv_bfloat16*)(smraw + SMEM_S);   // [64][SROWB]
    __nv_bfloat16* sW = (__nv_bfloat16*)(smraw + SMEM_W);   // [3][KCH][WROWB]
    float* sPQ = (float*)(smraw + SMEM_PQ);                 // [8][64]
    float* sPC = (float*)(smraw + SMEM_PC);                 // [8][64]

    const int tid  = threadIdx.x;
    const int warp = tid >> 5, lane = tid & 31;
    const int g = lane >> 2, t4 = lane & 3;
    const int wn = warp;                                    // 8 warps split N
    const long t0 = (long)blockIdx.x * MT;
    const int  l  = (int)(t0 >> 12);

    const int ncol0 = wn * 40;
    const int rF = (lane & 7) + ((lane >> 3) & 1) * 8;
    const int cF = (lane >> 4) * 8;

    // issue W chunks 0,1
    #pragma unroll
    for (int c = 0; c < 2; c++){
        const __nv_bfloat16* src = g_Wsb + c*KCH*NP;
        __nv_bfloat16* dst = sW + c*(KCH*WROWB);
        for (int i = tid; i < KCH*40; i += 256){
            int r = i / 40, cc = (i % 40) * 8;
            cp16(dst + r*WROWB + cc, src + r*NP + cc);
        }
        asm volatile("cp.async.commit_group;" ::: "memory");
    }

    // stage S tile (fp32 -> bf16), pad cols [300,320) with zero
    for (int i = tid; i < MT*40; i += 256){
        int row = i / 40, col = (i % 40) * 8;
        __nv_bfloat16* p = sS + row*SROWB + col;
        const float* srcp = sent + (t0 + row)*D_ + col;
        if (col + 8 <= D_){
            float4 a = *(const float4*)srcp, b = *(const float4*)(srcp + 4);
            p[0]=__float2bfloat16(a.x); p[1]=__float2bfloat16(a.y);
            p[2]=__float2bfloat16(a.z); p[3]=__float2bfloat16(a.w);
            p[4]=__float2bfloat16(b.x); p[5]=__float2bfloat16(b.y);
            p[6]=__float2bfloat16(b.z); p[7]=__float2bfloat16(b.w);
        } else {
            #pragma unroll
            for (int j = 0; j < 8; j++)
                p[j] = (col + j < D_) ? __float2bfloat16(srcp[j]) : __float2bfloat16(0.f);
        }
    }

    float acc[4][5][4];
    #pragma unroll
    for (int i=0;i<4;i++)
        #pragma unroll
        for (int j=0;j<5;j++)
            #pragma unroll
            for (int k=0;k<4;k++) acc[i][j][k] = 0.f;

    for (int ch = 0; ch < NCHUNKS; ch++){
        if (ch == NCHUNKS-1){ asm volatile("cp.async.wait_group 0;" ::: "memory"); }
        else                { asm volatile("cp.async.wait_group 1;" ::: "memory"); }
        __syncthreads();
        if (ch + 2 < NCHUNKS){
            const __nv_bfloat16* src = g_Wsb + (ch+2)*KCH*NP;
            __nv_bfloat16* dst = sW + ((ch+2)%3)*(KCH*WROWB);
            for (int i = tid; i < KCH*40; i += 256){
                int r = i / 40, cc = (i % 40) * 8;
                cp16(dst + r*WROWB + cc, src + r*NP + cc);
            }
            asm volatile("cp.async.commit_group;" ::: "memory");
        }
        const __nv_bfloat16* wbuf = sW + (ch%3)*(KCH*WROWB);
        const int kbase = ch * KCH;
        #pragma unroll
        for (int ks = 0; ks < KCH/16; ks++){
            const int k0s = kbase + ks*16;
            const int k0w = ks*16;
            unsigned b[5][2];
            ldmBT4(b[0][0],b[0][1],b[1][0],b[1][1], wbuf + (k0w + rF)*WROWB + ncol0 + cF);
            ldmBT4(b[2][0],b[2][1],b[3][0],b[3][1], wbuf + (k0w + rF)*WROWB + ncol0 + 16 + cF);
            ldmBT2(b[4][0],b[4][1],                 wbuf + (k0w + rF)*WROWB + ncol0 + 32);
            #pragma unroll
            for (int mf = 0; mf < 4; mf++){
                unsigned a0,a1,a2,a3;
                ldmA4(a0,a1,a2,a3, sS + (mf*16 + rF)*SROWB + k0s + cF);
                #pragma unroll
                for (int nf = 0; nf < 5; nf++)
                    asm volatile(
                        "mma.sync.aligned.m16n8k16.row.col.f32.bf16.bf16.f32 "
                        "{%0,%1,%2,%3},{%4,%5,%6,%7},{%8,%9},{%0,%1,%2,%3};"
                        : "+f"(acc[mf][nf][0]), "+f"(acc[mf][nf][1]),
                          "+f"(acc[mf][nf][2]), "+f"(acc[mf][nf][3])
                        : "r"(a0), "r"(a1), "r"(a2), "r"(a3),
                          "r"(b[nf][0]), "r"(b[nf][1]));
            }
        }
    }
    __syncthreads();

    // ---- epilogue: q[row] = z.s (s from smem), c[row] = z.s_next (gmem) ----
    const bool hn = (l < L_ - 1);
    #pragma unroll
    for (int mf = 0; mf < 4; mf++){
        #pragma unroll
        for (int h = 0; h < 2; h++){
            const int rloc = mf*16 + h*8 + g;
            const float* pnext = sent + (t0 + rloc + B_) * D_;
            float pq = 0.f, pc = 0.f;
            #pragma unroll
            for (int nf = 0; nf < 5; nf++){
                int e = ncol0 + nf*8 + 2*t4;
                if (e < D_){
                    float z0 = acc[mf][nf][h*2+0], z1 = acc[mf][nf][h*2+1];
                    __nv_bfloat162 s2 = *(const __nv_bfloat162*)(sS + rloc*SROWB + e);
                    pq += z0*__bfloat162float(s2.x) + z1*__bfloat162float(s2.y);
                    if (hn){
                        float2 n2 = *(const float2*)(pnext + e);
                        pc += z0*n2.x + z1*n2.y;
                    }
                }
            }
            pq += __shfl_xor_sync(0xffffffffu, pq, 1);
            pq += __shfl_xor_sync(0xffffffffu, pq, 2);
            pc += __shfl_xor_sync(0xffffffffu, pc, 1);
            pc += __shfl_xor_sync(0xffffffffu, pc, 2);
            if (t4 == 0){ sPQ[wn*MT + rloc] = pq; sPC[wn*MT + rloc] = pc; }
        }
    }
    __syncthreads();
    if (tid < MT){
        float v = 0.f;
        #pragma unroll
        for (int w = 0; w < 8; w++) v += sPQ[w*MT + tid];
        g_q[t0 + tid] = v;
    } else if (tid < 2*MT){
        int r = tid - MT;
        float v = 0.f;
        if (hn){
            #pragma unroll
            for (int w = 0; w < 8; w++) v += sPC[w*MT + r];
        }
        g_c[t0 + r] = v;
    }
}

// ---------------- pass 2: rolling-window softmax-combine (1 warp per batch col) ----------------
__global__ __launch_bounds__(256)
void pass2_combine(const float* __restrict__ sent, const int* __restrict__ size,
                   float* __restrict__ out){
    const int lane = threadIdx.x & 31;
    const int b = (blockIdx.x * blockDim.x + threadIdx.x) >> 5;
    if (b >= B_) return;
    const int sz = size[b];
    const float NEG = __int_as_float(0xff800000);
    const float INVD = 1.0f / (float)D_;
    const bool l3 = (lane < 11);  // 75 float4 per row: lanes hold j = lane, lane+32, lane+64(<75)

    const float4 Z4 = make_float4(0.f,0.f,0.f,0.f);
    float4 p0=Z4,p1=Z4,p2=Z4, c0,c1,c2, n0=Z4,n1=Z4,n2=Z4;

    const float4* row0 = (const float4*)(sent + (size_t)b * D_);
    c0 = row0[lane]; c1 = row0[lane+32]; c2 = l3 ? row0[lane+64] : Z4;
    const float4* row1 = (const float4*)(sent + (size_t)(B_ + b) * D_);
    n0 = row1[lane]; n1 = row1[lane+32]; n2 = l3 ? row1[lane+64] : Z4;

    float c_prev = 0.f;
    for (int l = 0; l < L_; l++){
        const int t = l*B_ + b;
        float c_cur = g_c[t];
        float l1 = g_q[t] * INVD;
        float l0 = (l >= 1   && l < sz    ) ? c_prev * INVD : NEG;
        float l2 = (l < L_-1 && l < sz - 1) ? c_cur  * INVD : NEG;
        float m  = fmaxf(l1, fmaxf(l0, l2));
        float e0 = __expf(l0 - m), e1 = __expf(l1 - m), e2 = __expf(l2 - m);
        float inv = 1.0f / (e0 + e1 + e2);
        float w0 = e0 * inv, w1 = e1 * inv, w2 = e2 * inv;

        float4* o = (float4*)(out + (size_t)t * D_);
        float4 v;
        v.x = w1*c0.x + w0*p0.x + w2*n0.x;
        v.y = w1*c0.y + w0*p0.y + w2*n0.y;
        v.z = w1*c0.z + w0*p0.z + w2*n0.z;
        v.w = w1*c0.w + w0*p0.w + w2*n0.w;
        o[lane] = v;
        v.x = w1*c1.x + w0*p1.x + w2*n1.x;
        v.y = w1*c1.y + w0*p1.y + w2*n1.y;
        v.z = w1*c1.z + w0*p1.z + w2*n1.z;
        v.w = w1*c1.w + w0*p1.w + w2*n1.w;
        o[lane+32] = v;
        if (l3){
            v.x = w1*c2.x + w0*p2.x + w2*n2.x;
            v.y = w1*c2.y + w0*p2.y + w2*n2.y;
            v.z = w1*c2.z + w0*p2.z + w2*n2.z;
            v.w = w1*c2.w + w0*p2.w + w2*n2.w;
            o[lane+64] = v;
        }
        // rotate window
        p0=c0; p1=c1; p2=c2;
        c0=n0; c1=n1; c2=n2;
        if (l + 2 < L_){
            const float4* rn = (const float4*)(sent + (size_t)((l+2)*B_ + b) * D_);
            n0 = rn[lane]; n1 = rn[lane+32]; n2 = l3 ? rn[lane+64] : Z4;
        } else {
            n0=Z4; n1=Z4; n2=Z4;
        }
        c_prev = c_cur;
    }
}

extern "C" void kernel_launch(void* const* d_in, const int* in_sizes, int n_in,
                              void* d_out, int out_size){
    const float* sent = nullptr;
    const int*   size = nullptr;
    const float* W    = nullptr;
    for (int i = 0; i < n_in; i++){
        if      (in_sizes[i] == L_*B_*D_) sent = (const float*)d_in[i];
        else if (in_sizes[i] == B_)       size = (const int*)d_in[i];
        else if (in_sizes[i] == D_*D_)    W    = (const float*)d_in[i];
    }
    float* out = (float*)d_out;

    cudaFuncSetAttribute(pass1_scores, cudaFuncAttributeMaxDynamicSharedMemorySize, SMEM_TOTAL);

    pass0_symW<<<(KP*NP + 255)/256, 256>>>(W);
    pass1_scores<<<T_/MT, 256, SMEM_TOTAL>>>(sent);
    pass2_combine<<<(B_*32)/256, 256>>>(sent, size, out);
}

// round 6
// speedup vs baseline: 2.2165x; 1.0625x over previous
#include <cuda_runtime.h>
#include <cuda_bf16.h>
#include <cstdint>

#define L_ 128
#define B_ 4096
#define D_ 300
#define T_ (L_*B_)          // 524288 tokens
#define KP 320              // staged K rows (10 chunks * 32); only 304 used in mma
#define NP 320              // padded N (8 warps * 40)
#define KCH 32              // K rows per chunk
#define NCHUNKS 10
#define MT 64               // tokens per block (M)
#define SROWB 328           // S smem row stride (bf16)
#define WROWB 328           // W smem row stride (bf16)

// smem layout (bytes)
#define SMEM_S  0                          // 64*328*2   = 41984
#define SMEM_W  41984                      // 3*32*328*2 = 62976  (reused as s_next tile in epilogue)
#define SMEM_PQ 104960                     // 8*64*4     = 2048
#define SMEM_PC 107008                     // 2048
#define SMEM_TOTAL 109056

__device__ __nv_bfloat16 g_Wsb[KP*NP];  // symmetrized bf16 [k][n], zero-padded
__device__ float g_q[T_];               // s^T Ws s
__device__ float g_c[T_];               // s_{l+1}^T Ws s_l (0 for l = L-1)

__device__ __forceinline__ void cp16(void* smem_dst, const void* gsrc){
    unsigned sa = (unsigned)__cvta_generic_to_shared(smem_dst);
    asm volatile("cp.async.cg.shared.global [%0], [%1], 16;" :: "r"(sa), "l"(gsrc));
}
__device__ __forceinline__ void ldmA4(unsigned& r0, unsigned& r1, unsigned& r2, unsigned& r3, const void* p){
    unsigned a = (unsigned)__cvta_generic_to_shared(p);
    asm volatile("ldmatrix.sync.aligned.m8n8.x4.shared.b16 {%0,%1,%2,%3},[%4];"
                 : "=r"(r0),"=r"(r1),"=r"(r2),"=r"(r3) : "r"(a));
}
__device__ __forceinline__ void ldmBT4(unsigned& r0, unsigned& r1, unsigned& r2, unsigned& r3, const void* p){
    unsigned a = (unsigned)__cvta_generic_to_shared(p);
    asm volatile("ldmatrix.sync.aligned.m8n8.x4.trans.shared.b16 {%0,%1,%2,%3},[%4];"
                 : "=r"(r0),"=r"(r1),"=r"(r2),"=r"(r3) : "r"(a));
}
__device__ __forceinline__ void ldmBT2(unsigned& r0, unsigned& r1, const void* p){
    unsigned a = (unsigned)__cvta_generic_to_shared(p);
    asm volatile("ldmatrix.sync.aligned.m8n8.x2.trans.shared.b16 {%0,%1},[%2];"
                 : "=r"(r0),"=r"(r1) : "r"(a));
}

// ---------------- pass 0: Wsb = bf16((W + W^T)/2), zero-padded [KP][NP] ----------------
__global__ void pass0_symW(const float* __restrict__ W){
    int idx = blockIdx.x * blockDim.x + threadIdx.x;
    if (idx >= KP*NP) return;
    int d = idx / NP, e = idx % NP;
    float v = 0.f;
    if (d < D_ && e < D_) v = 0.5f * (W[d*D_ + e] + W[e*D_ + d]);
    g_Wsb[idx] = __float2bfloat16(v);
}

// ---------------- pass 1: fused GEMM (Z = S*Ws) + row dots -> q, c ----------------
__global__ __launch_bounds__(256, 2)
void pass1_scores(const float* __restrict__ sent){
    extern __shared__ __align__(16) unsigned char smraw[];
    __nv_bfloat16* sS = (__nv_bfloat16*)(smraw + SMEM_S);   // [64][SROWB]
    __nv_bfloat16* sW = (__nv_bfloat16*)(smraw + SMEM_W);   // [3][KCH][WROWB]
    float* sPQ = (float*)(smraw + SMEM_PQ);                 // [8][64]
    float* sPC = (float*)(smraw + SMEM_PC);                 // [8][64]

    const int tid  = threadIdx.x;
    const int warp = tid >> 5, lane = tid & 31;
    const int g = lane >> 2, t4 = lane & 3;
    const int wn = warp;                                    // 8 warps split N
    const long t0 = (long)blockIdx.x * MT;
    const int  l  = (int)(t0 >> 12);

    const int ncol0 = wn * 40;
    const int rF = (lane & 7) + ((lane >> 3) & 1) * 8;
    const int cF = (lane >> 4) * 8;

    // issue W chunks 0,1
    #pragma unroll
    for (int c = 0; c < 2; c++){
        const __nv_bfloat16* src = g_Wsb + c*KCH*NP;
        __nv_bfloat16* dst = sW + c*(KCH*WROWB);
        for (int i = tid; i < KCH*40; i += 256){
            int r = i / 40, cc = (i % 40) * 8;
            cp16(dst + r*WROWB + cc, src + r*NP + cc);
        }
        asm volatile("cp.async.commit_group;" ::: "memory");
    }

    // stage S tile (fp32 -> bf16), pad cols [300,320) with zero
    for (int i = tid; i < MT*40; i += 256){
        int row = i / 40, col = (i % 40) * 8;
        __nv_bfloat16* p = sS + row*SROWB + col;
        const float* srcp = sent + (t0 + row)*D_ + col;
        if (col + 8 <= D_){
            float4 a = *(const float4*)srcp, b = *(const float4*)(srcp + 4);
            p[0]=__float2bfloat16(a.x); p[1]=__float2bfloat16(a.y);
            p[2]=__float2bfloat16(a.z); p[3]=__float2bfloat16(a.w);
            p[4]=__float2bfloat16(b.x); p[5]=__float2bfloat16(b.y);
            p[6]=__float2bfloat16(b.z); p[7]=__float2bfloat16(b.w);
        } else {
            #pragma unroll
            for (int j = 0; j < 8; j++)
                p[j] = (col + j < D_) ? __float2bfloat16(srcp[j]) : __float2bfloat16(0.f);
        }
    }

    float acc[4][5][4];
    #pragma unroll
    for (int i=0;i<4;i++)
        #pragma unroll
        for (int j=0;j<5;j++)
            #pragma unroll
            for (int k=0;k<4;k++) acc[i][j][k] = 0.f;

    for (int ch = 0; ch < NCHUNKS; ch++){
        if (ch == NCHUNKS-1){ asm volatile("cp.async.wait_group 0;" ::: "memory"); }
        else                { asm volatile("cp.async.wait_group 1;" ::: "memory"); }
        __syncthreads();
        if (ch + 2 < NCHUNKS){
            const __nv_bfloat16* src = g_Wsb + (ch+2)*KCH*NP;
            __nv_bfloat16* dst = sW + ((ch+2)%3)*(KCH*WROWB);
            for (int i = tid; i < KCH*40; i += 256){
                int r = i / 40, cc = (i % 40) * 8;
                cp16(dst + r*WROWB + cc, src + r*NP + cc);
            }
            asm volatile("cp.async.commit_group;" ::: "memory");
        }
        const __nv_bfloat16* wbuf = sW + (ch%3)*(KCH*WROWB);
        const int kbase = ch * KCH;
        const int kc = (ch == NCHUNKS-1) ? 1 : 2;   // K trimmed to 304: last chunk 1 kstep
        for (int ks = 0; ks < kc; ks++){
            const int k0s = kbase + ks*16;
            const int k0w = ks*16;
            unsigned b[5][2];
            ldmBT4(b[0][0],b[0][1],b[1][0],b[1][1], wbuf + (k0w + rF)*WROWB + ncol0 + cF);
            ldmBT4(b[2][0],b[2][1],b[3][0],b[3][1], wbuf + (k0w + rF)*WROWB + ncol0 + 16 + cF);
            ldmBT2(b[4][0],b[4][1],                 wbuf + (k0w + rF)*WROWB + ncol0 + 32);
            #pragma unroll
            for (int mf = 0; mf < 4; mf++){
                unsigned a0,a1,a2,a3;
                ldmA4(a0,a1,a2,a3, sS + (mf*16 + rF)*SROWB + k0s + cF);
                #pragma unroll
                for (int nf = 0; nf < 5; nf++)
                    asm volatile(
                        "mma.sync.aligned.m16n8k16.row.col.f32.bf16.bf16.f32 "
                        "{%0,%1,%2,%3},{%4,%5,%6,%7},{%8,%9},{%0,%1,%2,%3};"
                        : "+f"(acc[mf][nf][0]), "+f"(acc[mf][nf][1]),
                          "+f"(acc[mf][nf][2]), "+f"(acc[mf][nf][3])
                        : "r"(a0), "r"(a1), "r"(a2), "r"(a3),
                          "r"(b[nf][0]), "r"(b[nf][1]));
            }
        }
    }
    __syncthreads();

    // ---- stage s_next tile into sW area (coalesced), then dots from smem ----
    const bool hn = (l < L_ - 1);
    __nv_bfloat16* sN = sW;                                 // [64][SROWB] reuse
    if (hn){
        for (int i = tid; i < MT*40; i += 256){
            int row = i / 40, col = (i % 40) * 8;
            __nv_bfloat16* p = sN + row*SROWB + col;
            const float* srcp = sent + (t0 + B_ + row)*D_ + col;
            if (col + 8 <= D_){
                float4 a = *(const float4*)srcp, b = *(const float4*)(srcp + 4);
                p[0]=__float2bfloat16(a.x); p[1]=__float2bfloat16(a.y);
                p[2]=__float2bfloat16(a.z); p[3]=__float2bfloat16(a.w);
                p[4]=__float2bfloat16(b.x); p[5]=__float2bfloat16(b.y);
                p[6]=__float2bfloat16(b.z); p[7]=__float2bfloat16(b.w);
            } else {
                #pragma unroll
                for (int j = 0; j < 8; j++)
                    p[j] = (col + j < D_) ? __float2bfloat16(srcp[j]) : __float2bfloat16(0.f);
            }
        }
    }
    __syncthreads();

    #pragma unroll
    for (int mf = 0; mf < 4; mf++){
        #pragma unroll
        for (int h = 0; h < 2; h++){
            const int rloc = mf*16 + h*8 + g;
            float pq = 0.f, pc = 0.f;
            #pragma unroll
            for (int nf = 0; nf < 5; nf++){
                int e = ncol0 + nf*8 + 2*t4;
                if (e < D_){
                    float z0 = acc[mf][nf][h*2+0], z1 = acc[mf][nf][h*2+1];
                    __nv_bfloat162 s2 = *(const __nv_bfloat162*)(sS + rloc*SROWB + e);
                    pq += z0*__bfloat162float(s2.x) + z1*__bfloat162float(s2.y);
                    __nv_bfloat162 n2 = *(const __nv_bfloat162*)(sN + rloc*SROWB + e);
                    pc += z0*__bfloat162float(n2.x) + z1*__bfloat162float(n2.y);
                }
            }
            pq += __shfl_xor_sync(0xffffffffu, pq, 1);
            pq += __shfl_xor_sync(0xffffffffu, pq, 2);
            pc += __shfl_xor_sync(0xffffffffu, pc, 1);
            pc += __shfl_xor_sync(0xffffffffu, pc, 2);
            if (t4 == 0){ sPQ[wn*MT + rloc] = pq; sPC[wn*MT + rloc] = pc; }
        }
    }
    __syncthreads();
    if (tid < MT){
        float v = 0.f;
        #pragma unroll
        for (int w = 0; w < 8; w++) v += sPQ[w*MT + tid];
        g_q[t0 + tid] = v;
    } else if (tid < 2*MT){
        int r = tid - MT;
        float v = 0.f;
        if (hn){
            #pragma unroll
            for (int w = 0; w < 8; w++) v += sPC[w*MT + r];
        }
        g_c[t0 + r] = v;
    }
}

// ---------------- pass 2: rolling-window softmax-combine (1 warp per batch col) ----------------
__global__ __launch_bounds__(256)
void pass2_combine(const float* __restrict__ sent, const int* __restrict__ size,
                   float* __restrict__ out){
    const int lane = threadIdx.x & 31;
    const int b = (blockIdx.x * blockDim.x + threadIdx.x) >> 5;
    if (b >= B_) return;
    const int sz = size[b];
    const float NEG = __int_as_float(0xff800000);
    const float INVD = 1.0f / (float)D_;
    const bool l3 = (lane < 11);  // 75 float4 per row

    const float4 Z4 = make_float4(0.f,0.f,0.f,0.f);
    float4 p0=Z4,p1=Z4,p2=Z4, c0,c1,c2, n0=Z4,n1=Z4,n2=Z4;

    const float4* row0 = (const float4*)(sent + (size_t)b * D_);
    c0 = row0[lane]; c1 = row0[lane+32]; c2 = l3 ? row0[lane+64] : Z4;
    const float4* row1 = (const float4*)(sent + (size_t)(B_ + b) * D_);
    n0 = row1[lane]; n1 = row1[lane+32]; n2 = l3 ? row1[lane+64] : Z4;

    float c_prev = 0.f;
    for (int l = 0; l < L_; l++){
        const int t = l*B_ + b;
        float c_cur = g_c[t];
        float l1 = g_q[t] * INVD;
        float l0 = (l >= 1   && l < sz    ) ? c_prev * INVD : NEG;
        float l2 = (l < L_-1 && l < sz - 1) ? c_cur  * INVD : NEG;
        float m  = fmaxf(l1, fmaxf(l0, l2));
        float e0 = __expf(l0 - m), e1 = __expf(l1 - m), e2 = __expf(l2 - m);
        float inv = 1.0f / (e0 + e1 + e2);
        float w0 = e0 * inv, w1 = e1 * inv, w2 = e2 * inv;

        float4* o = (float4*)(out + (size_t)t * D_);
        float4 v;
        v.x = w1*c0.x + w0*p0.x + w2*n0.x;
        v.y = w1*c0.y + w0*p0.y + w2*n0.y;
        v.z = w1*c0.z + w0*p0.z + w2*n0.z;
        v.w = w1*c0.w + w0*p0.w + w2*n0.w;
        o[lane] = v;
        v.x = w1*c1.x + w0*p1.x + w2*n1.x;
        v.y = w1*c1.y + w0*p1.y + w2*n1.y;
        v.z = w1*c1.z + w0*p1.z + w2*n1.z;
        v.w = w1*c1.w + w0*p1.w + w2*n1.w;
        o[lane+32] = v;
        if (l3){
            v.x = w1*c2.x + w0*p2.x + w2*n2.x;
            v.y = w1*c2.y + w0*p2.y + w2*n2.y;
            v.z = w1*c2.z + w0*p2.z + w2*n2.z;
            v.w = w1*c2.w + w0*p2.w + w2*n2.w;
            o[lane+64] = v;
        }
        p0=c0; p1=c1; p2=c2;
        c0=n0; c1=n1; c2=n2;
        if (l + 2 < L_){
            const float4* rn = (const float4*)(sent + (size_t)((l+2)*B_ + b) * D_);
            n0 = rn[lane]; n1 = rn[lane+32]; n2 = l3 ? rn[lane+64] : Z4;
        } else {
            n0=Z4; n1=Z4; n2=Z4;
        }
        c_prev = c_cur;
    }
}

extern "C" void kernel_launch(void* const* d_in, const int* in_sizes, int n_in,
                              void* d_out, int out_size){
    const float* sent = nullptr;
    const int*   size = nullptr;
    const float* W    = nullptr;
    for (int i = 0; i < n_in; i++){
        if      (in_sizes[i] == L_*B_*D_) sent = (const float*)d_in[i];
        else if (in_sizes[i] == B_)       size = (const int*)d_in[i];
        else if (in_sizes[i] == D_*D_)    W    = (const float*)d_in[i];
    }
    float* out = (float*)d_out;

    cudaFuncSetAttribute(pass1_scores, cudaFuncAttributeMaxDynamicSharedMemorySize, SMEM_TOTAL);

    pass0_symW<<<(KP*NP + 255)/256, 256>>>(W);
    pass1_scores<<<T_/MT, 256, SMEM_TOTAL>>>(sent);
    pass2_combine<<<(B_*32)/256, 256>>>(sent, size, out);
}

// round 7
// speedup vs baseline: 2.4348x; 1.0985x over previous
#include <cuda_runtime.h>
#include <cuda_bf16.h>
#include <cstdint>

#define L_ 128
#define B_ 4096
#define D_ 300
#define T_ (L_*B_)          // 524288 tokens
#define KK 304              // K rows (19 ksteps of 16)
#define NP 320              // Ws row length (N), cols 300..319 zero
#define NH 160              // N cols per CTA half
#define WR2 168             // W smem row stride (bf16): 336B, 16B-aligned rows, conflict-free
#define SR2 312             // S smem row stride (bf16): 624B, conflict-free
#define MT 64               // tokens per b-chunk

// smem layout (bytes)
#define SMEM_W  0           // 304*168*2 = 102144
#define SMEM_S0 102144      // 64*312*2  = 39936
#define SMEM_S1 142080      // 39936
#define SMEM_PQ 182016      // 4*64*4 = 1024
#define SMEM_PC 183040      // 1024
#define SMEM_TOTAL 184064

__device__ __nv_bfloat16 g_Wsb[KK*NP];  // symmetrized bf16 [k][n]
__device__ float g_q2[2*T_];            // per-N-half partial of s^T Ws s
__device__ float g_c2[2*T_];            // per-N-half partial of s_{l+1}^T Ws s_l

__device__ __forceinline__ void cp16(void* smem_dst, const void* gsrc){
    unsigned sa = (unsigned)__cvta_generic_to_shared(smem_dst);
    asm volatile("cp.async.cg.shared.global [%0], [%1], 16;" :: "r"(sa), "l"(gsrc));
}
__device__ __forceinline__ void ldmA4(unsigned& r0, unsigned& r1, unsigned& r2, unsigned& r3, const void* p){
    unsigned a = (unsigned)__cvta_generic_to_shared(p);
    asm volatile("ldmatrix.sync.aligned.m8n8.x4.shared.b16 {%0,%1,%2,%3},[%4];"
                 : "=r"(r0),"=r"(r1),"=r"(r2),"=r"(r3) : "r"(a));
}
__device__ __forceinline__ void ldmBT4(unsigned& r0, unsigned& r1, unsigned& r2, unsigned& r3, const void* p){
    unsigned a = (unsigned)__cvta_generic_to_shared(p);
    asm volatile("ldmatrix.sync.aligned.m8n8.x4.trans.shared.b16 {%0,%1,%2,%3},[%4];"
                 : "=r"(r0),"=r"(r1),"=r"(r2),"=r"(r3) : "r"(a));
}
__device__ __forceinline__ void ldmBT2(unsigned& r0, unsigned& r1, const void* p){
    unsigned a = (unsigned)__cvta_generic_to_shared(p);
    asm volatile("ldmatrix.sync.aligned.m8n8.x2.trans.shared.b16 {%0,%1},[%2];"
                 : "=r"(r0),"=r"(r1) : "r"(a));
}

// ---------------- pass 0: Wsb = bf16((W + W^T)/2), [KK][NP], cols>=300 zero ----------------
__global__ void pass0_symW(const float* __restrict__ W){
    int idx = blockIdx.x * blockDim.x + threadIdx.x;
    if (idx >= KK*NP) return;
    int d = idx / NP, e = idx % NP;
    float v = 0.f;
    if (d < D_ && e < D_) v = 0.5f * (W[d*D_ + e] + W[e*D_ + d]);
    g_Wsb[idx] = __float2bfloat16(v);
}

// ---------------- pass 1: persistent fused GEMM + dots ----------------
__global__ __launch_bounds__(512, 1)
void pass1_scores(const float* __restrict__ sent){
    extern __shared__ __align__(16) unsigned char smraw[];
    __nv_bfloat16* sW  = (__nv_bfloat16*)(smraw + SMEM_W);
    __nv_bfloat16* sS0 = (__nv_bfloat16*)(smraw + SMEM_S0);
    __nv_bfloat16* sS1 = (__nv_bfloat16*)(smraw + SMEM_S1);
    float* sPQ = (float*)(smraw + SMEM_PQ);   // [4][64]
    float* sPC = (float*)(smraw + SMEM_PC);   // [4][64]

    const int tid  = threadIdx.x;
    const int warp = tid >> 5, lane = tid & 31;
    const int g = lane >> 2, t4 = lane & 3;
    const int wm = warp >> 2, wn = warp & 3;        // 4M x 4N warp grid
    const int nh = blockIdx.x & 1;                  // N half
    const int bc = blockIdx.x >> 1;                 // b-chunk
    const long base = (long)bc * MT;

    const int rF = (lane & 7) + ((lane >> 3) & 1) * 8;
    const int cF = (lane >> 4) * 8;

    // stage resident W half: rows k=0..303, cols nh*160..+160
    for (int i = tid; i < KK*20; i += 512){
        int k = i / 20, c = (i % 20) * 8;
        cp16(sW + k*WR2 + c, g_Wsb + k*NP + nh*NH + c);
    }
    asm volatile("cp.async.commit_group;" ::: "memory");

    // stage S tiles for l=0 (S0) and l=1 (S1), pad cols 300..303 zero
    #pragma unroll
    for (int lb = 0; lb < 2; lb++){
        __nv_bfloat16* dst = lb ? sS1 : sS0;
        for (int i = tid; i < MT*38; i += 512){
            int row = i / 38, col = (i % 38) * 8;
            __nv_bfloat16* p = dst + row*SR2 + col;
            const float* sp = sent + ((size_t)lb*B_ + base + row)*D_ + col;
            if (col + 8 <= D_){
                float4 a = *(const float4*)sp, b = *(const float4*)(sp + 4);
                p[0]=__float2bfloat16(a.x); p[1]=__float2bfloat16(a.y);
                p[2]=__float2bfloat16(a.z); p[3]=__float2bfloat16(a.w);
                p[4]=__float2bfloat16(b.x); p[5]=__float2bfloat16(b.y);
                p[6]=__float2bfloat16(b.z); p[7]=__float2bfloat16(b.w);
            } else {
                #pragma unroll
                for (int j = 0; j < 8; j++)
                    p[j] = (col + j < D_) ? __float2bfloat16(sp[j]) : __float2bfloat16(0.f);
            }
        }
    }
    asm volatile("cp.async.wait_group 0;" ::: "memory");
    __syncthreads();

    float4 pf[10];
    for (int l = 0; l < L_; l++){
        __nv_bfloat16* cur = (l & 1) ? sS1 : sS0;
        __nv_bfloat16* nxt = (l & 1) ? sS0 : sS1;
        const bool pfv = (l + 2 < L_);

        // 1. prefetch S_{l+2} (f32) into registers
        if (pfv){
            const float* srcb = sent + ((size_t)(l+2)*B_ + base)*D_;
            #pragma unroll
            for (int j = 0; j < 10; j++){
                int idx = tid + j*512;
                if (idx < MT*75){
                    int row = idx / 75, c4 = idx - row*75;
                    pf[j] = *(const float4*)(srcb + row*D_ + c4*4);
                }
            }
        }

        // 2. mma: acc[nf][4] over this warp's 16 rows x 40 cols
        float acc[5][4];
        #pragma unroll
        for (int i=0;i<5;i++){ acc[i][0]=0.f; acc[i][1]=0.f; acc[i][2]=0.f; acc[i][3]=0.f; }
        #pragma unroll
        for (int ks = 0; ks < 19; ks++){
            unsigned a0,a1,a2,a3;
            ldmA4(a0,a1,a2,a3, cur + (wm*16 + rF)*SR2 + ks*16 + cF);
            const __nv_bfloat16* wrow = sW + (ks*16 + rF)*WR2 + wn*40;
            unsigned b[5][2];
            ldmBT4(b[0][0],b[0][1],b[1][0],b[1][1], wrow + cF);
            ldmBT4(b[2][0],b[2][1],b[3][0],b[3][1], wrow + 16 + cF);
            ldmBT2(b[4][0],b[4][1],                 wrow + 32);
            #pragma unroll
            for (int nf = 0; nf < 5; nf++)
                asm volatile(
                    "mma.sync.aligned.m16n8k16.row.col.f32.bf16.bf16.f32 "
                    "{%0,%1,%2,%3},{%4,%5,%6,%7},{%8,%9},{%0,%1,%2,%3};"
                    : "+f"(acc[nf][0]), "+f"(acc[nf][1]), "+f"(acc[nf][2]), "+f"(acc[nf][3])
                    : "r"(a0), "r"(a1), "r"(a2), "r"(a3),
                      "r"(b[nf][0]), "r"(b[nf][1]));
        }

        // 3. dots: q = z.s_l (cur), c = z.s_{l+1} (nxt)
        #pragma unroll
        for (int h = 0; h < 2; h++){
            const int row = wm*16 + h*8 + g;
            float pq = 0.f, pc = 0.f;
            #pragma unroll
            for (int nf = 0; nf < 5; nf++){
                int eg = nh*NH + wn*40 + nf*8 + 2*t4;
                if (eg < D_){
                    float z0 = acc[nf][h*2+0], z1 = acc[nf][h*2+1];
                    __nv_bfloat162 s2 = *(const __nv_bfloat162*)(cur + row*SR2 + eg);
                    pq += z0*__bfloat162float(s2.x) + z1*__bfloat162float(s2.y);
                    __nv_bfloat162 n2 = *(const __nv_bfloat162*)(nxt + row*SR2 + eg);
                    pc += z0*__bfloat162float(n2.x) + z1*__bfloat162float(n2.y);
                }
            }
            pq += __shfl_xor_sync(0xffffffffu, pq, 1);
            pq += __shfl_xor_sync(0xffffffffu, pq, 2);
            pc += __shfl_xor_sync(0xffffffffu, pc, 1);
            pc += __shfl_xor_sync(0xffffffffu, pc, 2);
            if (t4 == 0){ sPQ[wn*MT + row] = pq; sPC[wn*MT + row] = pc; }
        }
        __syncthreads();

        const size_t t0 = (size_t)l*B_ + base;
        if (tid < MT){
            g_q2[(size_t)nh*T_ + t0 + tid] = sPQ[tid] + sPQ[MT+tid] + sPQ[2*MT+tid] + sPQ[3*MT+tid];
        } else if (tid < 2*MT){
            int r = tid - MT;
            float v = (l < L_-1) ? (sPC[r] + sPC[MT+r] + sPC[2*MT+r] + sPC[3*MT+r]) : 0.f;
            g_c2[(size_t)nh*T_ + t0 + r] = v;
        }

        // 4. commit prefetched S_{l+2} into retiring buffer (cur)
        if (pfv){
            #pragma unroll
            for (int j = 0; j < 10; j++){
                int idx = tid + j*512;
                if (idx < MT*75){
                    int row = idx / 75, c4 = idx - row*75;
                    __nv_bfloat16* p = cur + row*SR2 + c4*4;
                    p[0]=__float2bfloat16(pf[j].x); p[1]=__float2bfloat16(pf[j].y);
                    p[2]=__float2bfloat16(pf[j].z); p[3]=__float2bfloat16(pf[j].w);
                }
            }
        }
        __syncthreads();
    }
}

// ---------------- pass 2: rolling-window softmax-combine (1 warp per batch col) ----------------
__global__ __launch_bounds__(256)
void pass2_combine(const float* __restrict__ sent, const int* __restrict__ size,
                   float* __restrict__ out){
    const int lane = threadIdx.x & 31;
    const int b = (blockIdx.x * blockDim.x + threadIdx.x) >> 5;
    if (b >= B_) return;
    const int sz = size[b];
    const float NEG = __int_as_float(0xff800000);
    const float INVD = 1.0f / (float)D_;
    const bool l3 = (lane < 11);

    const float4 Z4 = make_float4(0.f,0.f,0.f,0.f);
    float4 p0=Z4,p1=Z4,p2=Z4, c0,c1,c2, n0=Z4,n1=Z4,n2=Z4;

    const float4* row0 = (const float4*)(sent + (size_t)b * D_);
    c0 = row0[lane]; c1 = row0[lane+32]; c2 = l3 ? row0[lane+64] : Z4;
    const float4* row1 = (const float4*)(sent + (size_t)(B_ + b) * D_);
    n0 = row1[lane]; n1 = row1[lane+32]; n2 = l3 ? row1[lane+64] : Z4;

    float c_prev = 0.f;
    for (int l = 0; l < L_; l++){
        const int t = l*B_ + b;
        float c_cur = g_c2[t] + g_c2[T_ + t];
        float qv    = g_q2[t] + g_q2[T_ + t];
        float l1 = qv * INVD;
        float l0 = (l >= 1   && l < sz    ) ? c_prev * INVD : NEG;
        float l2 = (l < L_-1 && l < sz - 1) ? c_cur  * INVD : NEG;
        float m  = fmaxf(l1, fmaxf(l0, l2));
        float e0 = __expf(l0 - m), e1 = __expf(l1 - m), e2 = __expf(l2 - m);
        float inv = 1.0f / (e0 + e1 + e2);
        float w0 = e0 * inv, w1 = e1 * inv, w2 = e2 * inv;

        float4* o = (float4*)(out + (size_t)t * D_);
        float4 v;
        v.x = w1*c0.x + w0*p0.x + w2*n0.x;
        v.y = w1*c0.y + w0*p0.y + w2*n0.y;
        v.z = w1*c0.z + w0*p0.z + w2*n0.z;
        v.w = w1*c0.w + w0*p0.w + w2*n0.w;
        o[lane] = v;
        v.x = w1*c1.x + w0*p1.x + w2*n1.x;
        v.y = w1*c1.y + w0*p1.y + w2*n1.y;
        v.z = w1*c1.z + w0*p1.z + w2*n1.z;
        v.w = w1*c1.w + w0*p1.w + w2*n1.w;
        o[lane+32] = v;
        if (l3){
            v.x = w1*c2.x + w0*p2.x + w2*n2.x;
            v.y = w1*c2.y + w0*p2.y + w2*n2.y;
            v.z = w1*c2.z + w0*p2.z + w2*n2.z;
            v.w = w1*c2.w + w0*p2.w + w2*n2.w;
            o[lane+64] = v;
        }
        p0=c0; p1=c1; p2=c2;
        c0=n0; c1=n1; c2=n2;
        if (l + 2 < L_){
            const float4* rn = (const float4*)(sent + (size_t)((l+2)*B_ + b) * D_);
            n0 = rn[lane]; n1 = rn[lane+32]; n2 = l3 ? rn[lane+64] : Z4;
        } else {
            n0=Z4; n1=Z4; n2=Z4;
        }
        c_prev = c_cur;
    }
}

extern "C" void kernel_launch(void* const* d_in, const int* in_sizes, int n_in,
                              void* d_out, int out_size){
    const float* sent = nullptr;
    const int*   size = nullptr;
    const float* W    = nullptr;
    for (int i = 0; i < n_in; i++){
        if      (in_sizes[i] == L_*B_*D_) sent = (const float*)d_in[i];
        else if (in_sizes[i] == B_)       size = (const int*)d_in[i];
        else if (in_sizes[i] == D_*D_)    W    = (const float*)d_in[i];
    }
    float* out = (float*)d_out;

    cudaFuncSetAttribute(pass1_scores, cudaFuncAttributeMaxDynamicSharedMemorySize, SMEM_TOTAL);

    pass0_symW<<<(KK*NP + 255)/256, 256>>>(W);
    pass1_scores<<<128, 512, SMEM_TOTAL>>>(sent);
    pass2_combine<<<(B_*32)/256, 256>>>(sent, size, out);
}